// round 17
// baseline (speedup 1.0000x reference)
#include <cuda_runtime.h>
#include <cstdint>

// FixedGaussianBlur: depthwise 21x21 Gaussian (sigma=3), reflect padding,
// x[32,3,512,512] f32 -> y[32,3,512,512] f32.
// R16 skeleton (59.5us best) with the tail fully flattened:
//  - tail rows 128-147 owned by warps 4-13 (2 rows each): loaded by owner,
//    filtered PRE-sync as 32 quarter-units (4 cols/lane, 84 FFMA-imm)
//  - no bar2, single __syncthreads
//  - load balance 8/10 rows per warp (was 8/15)

#define IMG_W 512
#define IMG_H 512
#define PAD 10
#define KS 21
#define TW 64
#define TH 128
#define SROWS 148
#define SCOLS 84
#define NTHREADS 512
#define NIMG 96
#define SMEM_BYTES (SROWS * SCOLS * 4)  // 49728

#define W0  0.13303900f
#define W1  0.12584950f
#define W2  0.10652928f
#define W3  0.08069223f
#define W4  0.05469397f
#define W5  0.03317359f
#define W6  0.01800488f
#define W7  0.00874446f
#define W8  0.00380033f
#define W9  0.00147793f
#define W10 0.00051432f

__device__ __forceinline__ float tap(int j) {
    constexpr float w[KS] = {W10, W9, W8, W7, W6, W5, W4, W3, W2, W1, W0,
                             W1, W2, W3, W4, W5, W6, W7, W8, W9, W10};
    return w[j];
}

__device__ __forceinline__ int reflect_idx(int i, int n) {
    i = (i < 0) ? -i : i;
    i = (i >= n) ? (2 * n - 2 - i) : i;
    return i;
}

__device__ __forceinline__ uint64_t bcast2(float f) {
    uint32_t b = __float_as_uint(f);
    return ((uint64_t)b << 32) | (uint64_t)b;
}

__device__ __forceinline__ void ffma2(uint64_t& d, uint64_t a, uint64_t b, uint64_t c) {
    asm("fma.rn.f32x2 %0, %1, %2, %3;" : "=l"(d) : "l"(a), "l"(b), "l"(c));
}

// Streaming 16-output horizontal filter: 9 LDS.128 -> 16 accumulators.
__device__ __forceinline__ void hfilter16s(const float* srow, float o[16]) {
    #pragma unroll
    for (int c = 0; c < 16; ++c) o[c] = 0.0f;
    const float4* p = reinterpret_cast<const float4*>(srow);
    #pragma unroll
    for (int q = 0; q < 9; ++q) {
        float4 t4 = p[q];
        #pragma unroll
        for (int c = 0; c < 16; ++c) {
            int j0 = 4 * q + 0 - c;
            int j1 = 4 * q + 1 - c;
            int j2 = 4 * q + 2 - c;
            int j3 = 4 * q + 3 - c;
            if (j0 >= 0 && j0 < KS) o[c] = fmaf(t4.x, tap(j0), o[c]);
            if (j1 >= 0 && j1 < KS) o[c] = fmaf(t4.y, tap(j1), o[c]);
            if (j2 >= 0 && j2 < KS) o[c] = fmaf(t4.z, tap(j2), o[c]);
            if (j3 >= 0 && j3 < KS) o[c] = fmaf(t4.w, tap(j3), o[c]);
        }
    }
}

// Streaming 4-output horizontal filter (tail quarter-unit): 6 LDS.128, 84 FMA.
__device__ __forceinline__ void hfilter4s(const float* srow, float o[4]) {
    #pragma unroll
    for (int c = 0; c < 4; ++c) o[c] = 0.0f;
    const float4* p = reinterpret_cast<const float4*>(srow);
    #pragma unroll
    for (int q = 0; q < 6; ++q) {
        float4 t4 = p[q];
        #pragma unroll
        for (int c = 0; c < 4; ++c) {
            int j0 = 4 * q + 0 - c;
            int j1 = 4 * q + 1 - c;
            int j2 = 4 * q + 2 - c;
            int j3 = 4 * q + 3 - c;
            if (j0 >= 0 && j0 < KS) o[c] = fmaf(t4.x, tap(j0), o[c]);
            if (j1 >= 0 && j1 < KS) o[c] = fmaf(t4.y, tap(j1), o[c]);
            if (j2 >= 0 && j2 < KS) o[c] = fmaf(t4.z, tap(j2), o[c]);
            if (j3 >= 0 && j3 < KS) o[c] = fmaf(t4.w, tap(j3), o[c]);
        }
    }
}

// Load one tile row r from gmem row reflect(y0-PAD+r), warp-cooperative.
__device__ __forceinline__ void load_row_int(float* s, const float* base,
                                             int y0, int x0, int r, int l) {
    int gy = reflect_idx(y0 - PAD + r, IMG_H);
    const uint64_t* g = reinterpret_cast<const uint64_t*>(
        base + (size_t)gy * IMG_W + (x0 - PAD));
    uint64_t* sp = reinterpret_cast<uint64_t*>(s) + r * (SCOLS / 2);
    sp[l] = __ldg(g + l);
    if (l < 10) sp[32 + l] = __ldg(g + 32 + l);
}

__device__ __forceinline__ void load_row_edge(float* s, const float* base,
                                              int y0, int x0, int r, int l) {
    int gy = reflect_idx(y0 - PAD + r, IMG_H);
    const float* g = base + (size_t)gy * IMG_W;
    #pragma unroll
    for (int c = l; c < SCOLS; c += 32) {
        int gx = reflect_idx(x0 - PAD + c, IMG_W);
        s[r * SCOLS + c] = __ldg(g + gx);
    }
}

__global__ __launch_bounds__(NTHREADS, 3)
void gauss_blur_fused(const float* __restrict__ in, float* __restrict__ out) {
    extern __shared__ __align__(16) float s[];   // [SROWS][SCOLS]

    const int tid = threadIdx.x;
    const int w = tid >> 5;
    const int l = tid & 31;
    const int x0 = blockIdx.x * TW;
    const int y0 = blockIdx.y * TH;
    const float* __restrict__ base = in + (size_t)blockIdx.z * (IMG_W * IMG_H);

    const bool x_int = (x0 >= PAD) && (x0 + TW + PAD <= IMG_W);

    // ---- Warp-owned row loading: warp w owns main rows 8w..8w+7; warps 4-13
    // additionally own 2 tail rows each (128+2(w-4), 129+2(w-4)). ----
    const int r0 = w << 3;
    const bool has_tail = (w >= 4) && (w <= 13);
    const int tb = 128 + ((w - 4) << 1);
    if (x_int) {
        #pragma unroll
        for (int rr = 0; rr < 8; ++rr) load_row_int(s, base, y0, x0, r0 + rr, l);
        if (has_tail) {
            load_row_int(s, base, y0, x0, tb, l);
            load_row_int(s, base, y0, x0, tb + 1, l);
        }
    } else {
        #pragma unroll
        for (int rr = 0; rr < 8; ++rr) load_row_edge(s, base, y0, x0, r0 + rr, l);
        if (has_tail) {
            load_row_edge(s, base, y0, x0, tb, l);
            load_row_edge(s, base, y0, x0, tb + 1, l);
        }
    }
    __syncwarp();

    // ---- Horizontal main round: rows 0..127, in place, warp-local sync ----
    // lane = seg*8 + dr: octet = 8 consecutive rows, one seg -> conflict-free.
    const int seg = (l >> 3) << 4;
    const int dr = l & 7;
    {
        const int row = r0 + dr;
        float o[16];
        hfilter16s(&s[row * SCOLS + seg], o);
        __syncwarp();
        float4* q = reinterpret_cast<float4*>(&s[row * SCOLS + seg]);
        q[0] = make_float4(o[0],  o[1],  o[2],  o[3]);
        q[1] = make_float4(o[4],  o[5],  o[6],  o[7]);
        q[2] = make_float4(o[8],  o[9],  o[10], o[11]);
        q[3] = make_float4(o[12], o[13], o[14], o[15]);
    }

    // ---- Horizontal tail round (warps 4-13), PRE-sync, warp-local ----
    // 2 rows x 16 quarter-units = 32 lanes: lane -> (row = tb + l/16,
    // out cols oc..oc+3 with oc = (l%16)*4).
    if (has_tail) {
        const int trow = tb + (l >> 4);
        const int oc = (l & 15) << 2;
        float o4[4];
        hfilter4s(&s[trow * SCOLS + oc], o4);
        __syncwarp();   // tail raw reads complete (rows are warp-owned)
        *reinterpret_cast<float4*>(&s[trow * SCOLS + oc]) =
            make_float4(o4[0], o4[1], o4[2], o4[3]);
    }

    __syncthreads();   // the ONLY barrier: entire h-tile (rows 0..147) ready

    // ---- Vertical pass: 32 col-pairs x 16 groups of 8 rows ----
    {
        const int cp = tid & 31;
        const int g = (tid >> 5) << 3;

        uint64_t acc[8];
        #pragma unroll
        for (int o = 0; o < 8; ++o) acc[o] = 0;

        const float* col = s + 2 * cp;
        #pragma unroll
        for (int t = 0; t < 28; ++t) {
            uint64_t v2 = *reinterpret_cast<const uint64_t*>(col + (g + t) * SCOLS);
            #pragma unroll
            for (int o = 0; o < 8; ++o) {
                int j = t - o;
                if (j >= 0 && j < KS) {
                    int wi = (j <= 10) ? j : (20 - j);
                    ffma2(acc[o], v2, bcast2(tap(wi)), acc[o]);
                }
            }
        }

        char* dst = (char*)(out + (size_t)blockIdx.z * (IMG_W * IMG_H)
                                + (size_t)(y0 + g) * IMG_W + (x0 + 2 * cp));
        #pragma unroll
        for (int o = 0; o < 8; ++o) {
            *reinterpret_cast<uint64_t*>(dst) = acc[o];
            dst += IMG_W * 4;
        }
    }
}

extern "C" void kernel_launch(void* const* d_in, const int* in_sizes, int n_in,
                              void* d_out, int out_size) {
    (void)in_sizes; (void)n_in; (void)out_size;
    const float* x = (const float*)d_in[0];
    float* y = (float*)d_out;
    cudaFuncSetAttribute(gauss_blur_fused,
                         cudaFuncAttributeMaxDynamicSharedMemorySize, SMEM_BYTES);
    dim3 grid(IMG_W / TW, IMG_H / TH, NIMG);  // 8 x 4 x 96
    gauss_blur_fused<<<grid, NTHREADS, SMEM_BYTES>>>(x, y);
}